// round 15
// baseline (speedup 1.0000x reference)
#include <cuda_runtime.h>
#include <cuda_fp16.h>
#include <math.h>
#include <stdint.h>

#define NRR   2000
#define NPP   1512
#define NMTOT 3512
#define MPAD  3584
#define KATT  3000
#define KFUN  5603
#define KATT_PAD 3008
#define KFUN_PAD 5632
#define HATT  2048
#define HFUN  4096
#define BATCH 8192
#define PROT  1512
#define SPL2  8

// ---------------- device scratch (fp16 GEMM path) ----------------
__device__ __align__(256) __half g_Ahi_att[(size_t)MPAD * KATT_PAD];
__device__ __align__(256) __half g_Alo_att[(size_t)MPAD * KATT_PAD];
__device__ __align__(256) __half g_Ahi_fun[(size_t)MPAD * KFUN_PAD];
__device__ __align__(256) __half g_Alo_fun[(size_t)MPAD * KFUN_PAD];
__device__ __align__(256) __half g_B_att[(size_t)HATT * KATT_PAD];
__device__ __align__(256) __half g_B_fun[(size_t)HFUN * KFUN_PAD];
// H in fp16 hi/lo: att rows [3584][2048] then fun rows [3584][4096]
__device__ __align__(256) __half g_Hhi[(size_t)MPAD * (HATT + HFUN)];
__device__ __align__(256) __half g_Hlo[(size_t)MPAD * (HATT + HFUN)];
// W2 transposed, single fp16
__device__ __align__(256) __half g_B2_att[(size_t)256 * HATT];
__device__ __align__(256) __half g_B2_fun[(size_t)256 * HFUN];
// split-K partials: [branch(2)][split(8)][3584][256]
__device__ float g_P[(size_t)2 * SPL2 * MPAD * 256];

__device__ __forceinline__ float gelu_f(float x) {
    return 0.5f * x * (1.0f + erff(x * 0.70710678118654752f));
}
__device__ __forceinline__ float sigmoid_f(float x) {
    return 1.0f / (1.0f + expf(-x));
}
__device__ __forceinline__ float leaky_f(float x) {
    return (x >= 0.f) ? x : 0.01f * x;
}

// ---- packed fp32x2 helpers (conv kernel) ----
__device__ __forceinline__ uint64_t pack2(float x) {
    uint64_t r; asm("mov.b64 %0, {%1, %1};" : "=l"(r) : "f"(x)); return r;
}
__device__ __forceinline__ uint64_t packf2(float lo, float hi) {
    uint64_t r; asm("mov.b64 %0, {%1, %2};" : "=l"(r) : "f"(lo), "f"(hi)); return r;
}
__device__ __forceinline__ void fma2(uint64_t& d, uint64_t a, uint64_t b) {
    asm("fma.rn.f32x2 %0, %1, %2, %0;" : "+l"(d) : "l"(a), "l"(b));
}
__device__ __forceinline__ float2 unpack2(uint64_t v) {
    float2 f; asm("mov.b64 {%0, %1}, %2;" : "=f"(f.x), "=f"(f.y) : "l"(v)); return f;
}

__device__ __forceinline__ uint32_t smem_u32(const void* p) {
    return (uint32_t)__cvta_generic_to_shared(p);
}
#define CPA16(dst, src) asm volatile("cp.async.cg.shared.global [%0], [%1], 16;" :: "r"(dst), "l"(src))
#define CPA_COMMIT()    asm volatile("cp.async.commit_group;")
#define CPA_WAIT2()     asm volatile("cp.async.wait_group 2;")

#define LDMX4(r, a) \
    asm volatile("ldmatrix.sync.aligned.m8n8.x4.shared.b16 {%0,%1,%2,%3}, [%4];" \
        : "=r"((r)[0]), "=r"((r)[1]), "=r"((r)[2]), "=r"((r)[3]) : "r"(a))

__device__ __forceinline__ void mma_fp16(float* d,
                                         uint32_t a0, uint32_t a1, uint32_t a2, uint32_t a3,
                                         uint32_t b0, uint32_t b1) {
    asm volatile(
        "mma.sync.aligned.m16n8k16.row.col.f32.f16.f16.f32 "
        "{%0,%1,%2,%3}, {%4,%5,%6,%7}, {%8,%9}, {%0,%1,%2,%3};"
        : "+f"(d[0]), "+f"(d[1]), "+f"(d[2]), "+f"(d[3])
        : "r"(a0), "r"(a1), "r"(a2), "r"(a3), "r"(b0), "r"(b1));
}

// ===========================================================================
// Prep 1: split fp32 activations (row-concat + pad) into fp16 hi/lo.
// blockIdx.z = 0 -> att, 1 -> fun. ONE launch.
// ===========================================================================
__global__ void split_cat2_kernel(const float* __restrict__ rA, const float* __restrict__ pA,
                                  const float* __restrict__ rF, const float* __restrict__ pF,
                                  __half* __restrict__ DhiA, __half* __restrict__ DloA,
                                  __half* __restrict__ DhiF, __half* __restrict__ DloF)
{
    const int br = blockIdx.z;
    const int K    = br ? KFUN : KATT;
    const int Kpad = br ? KFUN_PAD : KATT_PAD;
    const float* S0 = br ? rF : rA;
    const float* S1 = br ? pF : pA;
    __half* Dhi = br ? DhiF : DhiA;
    __half* Dlo = br ? DloF : DloA;

    int k = blockIdx.x * 256 + threadIdx.x;
    int m = blockIdx.y;
    if (k >= Kpad) return;
    float x = 0.f;
    if (k < K && m < NMTOT)
        x = (m < NRR) ? S0[(size_t)m * K + k] : S1[(size_t)(m - NRR) * K + k];
    __half hi = __float2half_rn(x);
    __half lo = __float2half_rn(x - __half2float(hi));
    Dhi[(size_t)m * Kpad + k] = hi;
    Dlo[(size_t)m * Kpad + k] = lo;
}

// ===========================================================================
// Prep 2: transpose weights W[K,N] -> single fp16 [N, Kpad].
// ===========================================================================
__global__ void tsplit_kernel(const float* __restrict__ W, int K, int N, int Kpad,
                              __half* __restrict__ D)
{
    __shared__ float tile[32][33];
    const int t = threadIdx.x;
    const int tx = t & 31, ty = t >> 5;
    const int kb = blockIdx.y * 32, nb = blockIdx.x * 32;
    #pragma unroll
    for (int r = 0; r < 4; r++) {
        int kl = ty + 8 * r;
        int gk = kb + kl;
        tile[kl][tx] = (gk < K) ? W[(size_t)gk * N + nb + tx] : 0.f;
    }
    __syncthreads();
    #pragma unroll
    for (int r = 0; r < 4; r++) {
        int nl = ty + 8 * r;
        D[(size_t)(nb + nl) * Kpad + kb + tx] = __float2half_rn(tile[tx][nl]);
    }
}

// ===========================================================================
// Shared mma.sync mainloop: CTA 128x128, 8 warps (4m x 2n), warp tile 32x64,
// BK=32 stages (Ahi|Alo|B 8KB each = 24KB), 4-stage cp.async pipeline,
// ldmatrix fragment loads, fp16 2-product split with DE-INTERLEAVED products
// (all 16 Ah*B MMAs, then all 16 Al*B MMAs -> no back-to-back same-acc RAW).
// ===========================================================================
#define G1_STAGE 24576
#define G1_SMEM  (4 * G1_STAGE)

__device__ __forceinline__ void mma_mainloop(
    uint32_t sb, int t,
    const __half* __restrict__ Ahi, const __half* __restrict__ Alo,
    const __half* __restrict__ B,
    int Kpad, int kb, int C, int m0, int n0,
    float acc[2][8][4])
{
    const int lane = t & 31;
    const int wid  = t >> 5;
    const int wm   = wid & 3;
    const int wn   = wid >> 2;

    auto load_stage = [&](int c, int s) {
        const int kc = kb + c * 32;
        const uint32_t dstb = sb + (uint32_t)s * G1_STAGE;
        #pragma unroll
        for (int j = 0; j < 6; j++) {
            int cg  = t + 256 * j;
            int mat = cg >> 9;              // 0:Ahi 1:Alo 2:B
            int idx = cg & 511;
            int row = idx >> 2;
            int ch  = idx & 3;
            int sw  = (row ^ (row >> 2)) & 3;
            uint32_t dst = dstb + (uint32_t)(mat * 8192 + row * 64 + ((ch ^ sw) << 4));
            const __half* src =
                (mat == 0 ? Ahi + (size_t)(m0 + row) * Kpad :
                 mat == 1 ? Alo + (size_t)(m0 + row) * Kpad :
                            B   + (size_t)(n0 + row) * Kpad) + kc + ch * 8;
            CPA16(dst, src);
        }
        CPA_COMMIT();
    };

    auto compute_stage = [&](int s) {
        const uint32_t Ab = sb + (uint32_t)s * G1_STAGE;
        #pragma unroll
        for (int kk = 0; kk < 2; kk++) {
            // ---- load ALL fragments for this kk up front ----
            uint32_t ah[2][4], al[2][4], bf[4][4];
            {
                uint32_t arow0 = (uint32_t)(wm * 32 + (lane & 7) + ((lane >> 3) & 1) * 8);
                uint32_t achnk = (uint32_t)(2 * kk + (lane >> 4));
                #pragma unroll
                for (int T = 0; T < 2; T++) {
                    uint32_t r  = arow0 + T * 16;
                    uint32_t sw = (r ^ (r >> 2)) & 3;
                    uint32_t a  = Ab + r * 64 + ((achnk ^ sw) << 4);
                    LDMX4(ah[T], a);
                    LDMX4(al[T], a + 8192);
                }
            }
            {
                uint32_t brow0 = (uint32_t)(wn * 64 + ((lane >> 4) & 1) * 8 + (lane & 7));
                uint32_t bchnk = (uint32_t)(2 * kk + ((lane >> 3) & 1));
                #pragma unroll
                for (int p = 0; p < 4; p++) {
                    uint32_t r  = brow0 + 16 * p;
                    uint32_t sw = (r ^ (r >> 2)) & 3;
                    LDMX4(bf[p], Ab + 16384 + r * 64 + ((bchnk ^ sw) << 4));
                }
            }
            // ---- product 1: Ah * B (16 independent accumulators) ----
            #pragma unroll
            for (int p = 0; p < 4; p++)
                #pragma unroll
                for (int hf = 0; hf < 2; hf++)
                    #pragma unroll
                    for (int T = 0; T < 2; T++)
                        mma_fp16(acc[T][2 * p + hf],
                                 ah[T][0], ah[T][1], ah[T][2], ah[T][3],
                                 bf[p][2 * hf], bf[p][2 * hf + 1]);
            // ---- product 2: Al * B ----
            #pragma unroll
            for (int p = 0; p < 4; p++)
                #pragma unroll
                for (int hf = 0; hf < 2; hf++)
                    #pragma unroll
                    for (int T = 0; T < 2; T++)
                        mma_fp16(acc[T][2 * p + hf],
                                 al[T][0], al[T][1], al[T][2], al[T][3],
                                 bf[p][2 * hf], bf[p][2 * hf + 1]);
        }
    };

    load_stage(0, 0);
    if (C > 1) load_stage(1, 1); else CPA_COMMIT();
    if (C > 2) load_stage(2, 2); else CPA_COMMIT();

    for (int c = 0; c < C; c++) {
        CPA_WAIT2();
        __syncthreads();
        if (c + 3 < C) load_stage(c + 3, (c + 3) & 3);
        else CPA_COMMIT();
        compute_stage(c & 3);
    }
}

// ===========================================================================
// GEMM1: H = gelu(X W1 + b1) -> fp16 hi/lo.  bx<16 att, else fun.
// ===========================================================================
__global__ __launch_bounds__(256, 2)
void gemm1_mma_kernel(const __half* __restrict__ AhiA, const __half* __restrict__ AloA,
                      const __half* __restrict__ BA, const float* __restrict__ biasA,
                      const __half* __restrict__ AhiF, const __half* __restrict__ AloF,
                      const __half* __restrict__ BF, const float* __restrict__ biasF,
                      __half* __restrict__ Hhi, __half* __restrict__ Hlo)
{
    extern __shared__ char smraw[];
    const uint32_t sb = smem_u32(smraw);
    const int t = threadIdx.x;
    const int lane = t & 31, wid = t >> 5, wm = wid & 3, wn = wid >> 2;
    const int g = lane >> 2, tq = lane & 3;
    const int m0 = blockIdx.y * 128;

    const __half *Ahi, *Alo, *B;
    const float* bias;
    __half *Hh, *Hl;
    int Kpad, ldH, n0;
    if (blockIdx.x < 16) {
        Ahi = AhiA; Alo = AloA; B = BA; bias = biasA;
        Hh = Hhi; Hl = Hlo; Kpad = KATT_PAD; ldH = HATT; n0 = blockIdx.x * 128;
    } else {
        Ahi = AhiF; Alo = AloF; B = BF; bias = biasF;
        Hh = Hhi + (size_t)MPAD * HATT; Hl = Hlo + (size_t)MPAD * HATT;
        Kpad = KFUN_PAD; ldH = HFUN; n0 = (blockIdx.x - 16) * 128;
    }

    float acc[2][8][4];
    #pragma unroll
    for (int T = 0; T < 2; T++)
        #pragma unroll
        for (int n8 = 0; n8 < 8; n8++)
            #pragma unroll
            for (int q = 0; q < 4; q++) acc[T][n8][q] = 0.f;

    mma_mainloop(sb, t, Ahi, Alo, B, Kpad, 0, Kpad >> 5, m0, n0, acc);

    // epilogue: gelu(bias+acc) -> fp16 hi/lo
    #pragma unroll
    for (int T = 0; T < 2; T++) {
        const int r0 = m0 + wm * 32 + T * 16 + g;
        const int r1 = r0 + 8;
        #pragma unroll
        for (int n8 = 0; n8 < 8; n8++) {
            const int col = n0 + wn * 64 + n8 * 8 + 2 * tq;
            const float b0 = bias[col], b1 = bias[col + 1];
            if (r0 < NMTOT) {
                float v0 = gelu_f(acc[T][n8][0] + b0);
                float v1 = gelu_f(acc[T][n8][1] + b1);
                __half2 h, l;
                h.x = __float2half_rn(v0); h.y = __float2half_rn(v1);
                l.x = __float2half_rn(v0 - __half2float(h.x));
                l.y = __float2half_rn(v1 - __half2float(h.y));
                *(__half2*)(Hh + (size_t)r0 * ldH + col) = h;
                *(__half2*)(Hl + (size_t)r0 * ldH + col) = l;
            }
            if (r1 < NMTOT) {
                float v0 = gelu_f(acc[T][n8][2] + b0);
                float v1 = gelu_f(acc[T][n8][3] + b1);
                __half2 h, l;
                h.x = __float2half_rn(v0); h.y = __float2half_rn(v1);
                l.x = __float2half_rn(v0 - __half2float(h.x));
                l.y = __float2half_rn(v1 - __half2float(h.y));
                *(__half2*)(Hh + (size_t)r1 * ldH + col) = h;
                *(__half2*)(Hl + (size_t)r1 * ldH + col) = l;
            }
        }
    }
}

// ===========================================================================
// GEMM2 (split-K partials): bx = branch*2 + ntile, bz = k-slice.
// ===========================================================================
__global__ __launch_bounds__(256, 2)
void gemm2_mma_kernel(const __half* __restrict__ Hhi, const __half* __restrict__ Hlo,
                      const __half* __restrict__ B2A, const __half* __restrict__ B2F,
                      float* __restrict__ P)
{
    extern __shared__ char smraw[];
    const uint32_t sb = smem_u32(smraw);
    const int t = threadIdx.x;
    const int lane = t & 31, wid = t >> 5, wm = wid & 3, wn = wid >> 2;
    const int g = lane >> 2, tq = lane & 3;
    const int m0 = blockIdx.y * 128;

    const int branch = blockIdx.x >> 1;
    const int n0     = (blockIdx.x & 1) * 128;
    const int sl     = blockIdx.z;

    const __half *Ahi, *Alo, *B;
    int K;
    if (branch == 0) {
        Ahi = Hhi; Alo = Hlo; B = B2A; K = HATT;
    } else {
        Ahi = Hhi + (size_t)MPAD * HATT; Alo = Hlo + (size_t)MPAD * HATT;
        B = B2F; K = HFUN;
    }
    const int chunk = K / SPL2;
    const int kb = sl * chunk;

    float acc[2][8][4];
    #pragma unroll
    for (int T = 0; T < 2; T++)
        #pragma unroll
        for (int n8 = 0; n8 < 8; n8++)
            #pragma unroll
            for (int q = 0; q < 4; q++) acc[T][n8][q] = 0.f;

    mma_mainloop(sb, t, Ahi, Alo, B, K, kb, chunk >> 5, m0, n0, acc);

    float* Pd = P + ((size_t)(branch * SPL2 + sl) * MPAD) * 256;
    #pragma unroll
    for (int T = 0; T < 2; T++) {
        const int r0 = m0 + wm * 32 + T * 16 + g;
        const int r1 = r0 + 8;
        #pragma unroll
        for (int n8 = 0; n8 < 8; n8++) {
            const int col = n0 + wn * 64 + n8 * 8 + 2 * tq;
            *(float2*)(Pd + (size_t)r0 * 256 + col) = make_float2(acc[T][n8][0], acc[T][n8][1]);
            *(float2*)(Pd + (size_t)r1 * 256 + col) = make_float2(acc[T][n8][2], acc[T][n8][3]);
        }
    }
}

// Reduce split-K partials (both branches), add bias, sigmoid -> e[3512,512].
__global__ void reduce2_kernel(const float* __restrict__ P,
                               const float* __restrict__ biasA,
                               const float* __restrict__ biasF,
                               float* __restrict__ e)
{
    int i = blockIdx.x * 256 + threadIdx.x;
    if (i >= NMTOT * 512) return;
    int m = i >> 9, n = i & 511;
    int br = n >> 8, col = n & 255;
    float v = br ? biasF[col] : biasA[col];
    #pragma unroll
    for (int s = 0; s < SPL2; s++)
        v += P[((size_t)(br * SPL2 + s) * MPAD + m) * 256 + col];
    e[i] = sigmoid_f(v);
}

// ---------------------------------------------------------------------------
// Fused per-sample conv pipeline (unchanged, proven).
// ---------------------------------------------------------------------------
#define SX_STRIDE 520
#define A1_STRIDE 264
#define W2_STRIDE 245

#define SMEM_FLOATS (2*SX_STRIDE + 32*A1_STRIDE + 32*W2_STRIDE + 240 + 16)

__global__ __launch_bounds__(256)
void conv_kernel(const float* __restrict__ e,
                 const int* __restrict__ idx,
                 const float* __restrict__ w1g,
                 const float* __restrict__ b1,
                 const float* __restrict__ w2g,
                 const float* __restrict__ b2,
                 const float* __restrict__ Wout,
                 const float* __restrict__ bout,
                 float* __restrict__ outp,
                 float* __restrict__ flat)
{
    extern __shared__ float sm[];
    float* sx  = sm;
    float* a1s = sx  + 2 * SX_STRIDE;
    float* w2s = a1s + 32 * A1_STRIDE;
    float* w1s = w2s + 32 * W2_STRIDE;
    float* red = w1s + 240;

    const int t = threadIdx.x;
    const int b = blockIdx.x;

    for (int i = t; i < 2 * SX_STRIDE;  i += 256) sx[i]  = 0.f;
    for (int i = t; i < 32 * A1_STRIDE; i += 256) a1s[i] = 0.f;
    for (int i = t; i < 240; i += 256) w1s[i] = w1g[i];
    for (int i = t; i < 32 * 240; i += 256) {
        int oc = i / 240, r = i - oc * 240;
        w2s[oc * W2_STRIDE + r] = w2g[i];
    }
    const int id  = idx[b];
    const int rno = id / PROT;
    const int pno = id % PROT;
    __syncthreads();

    {
        const float* er = e + (size_t)rno * 512;
        const float* ep = e + (size_t)(NRR + pno) * 512;
        for (int i = t; i < 512; i += 256) {
            sx[0 * SX_STRIDE + 2 + i] = er[i];
            sx[1 * SX_STRIDE + 2 + i] = ep[i];
        }
    }
    __syncthreads();

    for (int j = 0; j < 32; j++) {
        int i   = t + 256 * j;
        int c   = i >> 9;
        int rem = i & 511;
        int ph  = rem >> 8;
        int pw  = rem & 255;
        const float* w = w1s + c * 15;
        float bias1 = b1[c];
        float s = 0.f;
        #pragma unroll
        for (int dh = 0; dh < 2; dh++) {
            int oh = 2 * ph + dh;
            #pragma unroll
            for (int dw = 0; dw < 2; dw++) {
                int ow = 2 * pw + dw;
                float cv = bias1;
                #pragma unroll
                for (int ih = 0; ih < 2; ih++) {
                    int kh = ih - oh + 2;
                    if (kh >= 0 && kh <= 2) {
                        const float* xr = sx + ih * SX_STRIDE + ow;
                        #pragma unroll
                        for (int kw = 0; kw < 5; kw++)
                            cv = fmaf(xr[kw], w[kh * 5 + kw], cv);
                    }
                }
                s += leaky_f(cv);
            }
        }
        a1s[(c * 2 + ph) * A1_STRIDE + pw + 2] = 0.25f * s;
    }
    __syncthreads();

    const int ph2 = t >> 7;
    const int oc  = (t >> 2) & 31;
    const int q   = t & 3;
    const float bias2 = b2[oc];
    const float* wbase = w2s + oc * W2_STRIDE;

    float d0 = 0.f, d1 = 0.f;

    for (int it = 0; it < 8; it++) {
        const int chunk = it * 4 + q;
        const int pw0   = chunk * 4;
        const int iwoff = chunk * 8;

        uint64_t accp0[4], accp1[4];
        #pragma unroll
        for (int p = 0; p < 4; p++) { accp0[p] = 0ull; accp1[p] = 0ull; }

        for (int ci = 0; ci < 16; ci++) {
            uint64_t wp[15];
            {
                const float* w = wbase + ci * 15;
                #pragma unroll
                for (int k = 0; k < 15; k++) wp[k] = pack2(w[k]);
            }

            float r0f[12], r1f[12];
            {
                const float* p0 = a1s + (ci * 2 + 0) * A1_STRIDE + iwoff;
                const float* p1 = p0 + A1_STRIDE;
                #pragma unroll
                for (int v = 0; v < 3; v++) {
                    float4 u0 = *(const float4*)(p0 + 4 * v);
                    float4 u1 = *(const float4*)(p1 + 4 * v);
                    r0f[4*v] = u0.x; r0f[4*v+1] = u0.y; r0f[4*v+2] = u0.z; r0f[4*v+3] = u0.w;
                    r1f[4*v] = u1.x; r1f[4*v+1] = u1.y; r1f[4*v+2] = u1.z; r1f[4*v+3] = u1.w;
                }
            }
            uint64_t rp0[11], rp1[11];
            #pragma unroll
            for (int k = 0; k < 11; k++) {
                rp0[k] = packf2(r0f[k], r0f[k + 1]);
                rp1[k] = packf2(r1f[k], r1f[k + 1]);
            }

            if (ph2 == 0) {
                #pragma unroll
                for (int p = 0; p < 4; p++) {
                    const int j = 2 * p;
                    #pragma unroll
                    for (int kw = 0; kw < 5; kw++) {
                        fma2(accp0[p], rp0[j + kw], wp[10 + kw]);
                        fma2(accp1[p], rp0[j + kw], wp[5 + kw]);
                        fma2(accp1[p], rp1[j + kw], wp[10 + kw]);
                    }
                }
            } else {
                #pragma unroll
                for (int p = 0; p < 4; p++) {
                    const int j = 2 * p;
                    #pragma unroll
                    for (int kw = 0; kw < 5; kw++) {
                        fma2(accp0[p], rp0[j + kw], wp[kw]);
                        fma2(accp0[p], rp1[j + kw], wp[5 + kw]);
                        fma2(accp1[p], rp1[j + kw], wp[kw]);
                    }
                }
            }
        }

        float fl[4];
        #pragma unroll
        for (int p = 0; p < 4; p++) {
            float2 v0 = unpack2(accp0[p]);
            float2 v1 = unpack2(accp1[p]);
            float l0 = leaky_f(v0.x + bias2);
            float l1 = leaky_f(v0.y + bias2);
            float l2 = leaky_f(v1.x + bias2);
            float l3 = leaky_f(v1.y + bias2);
            float m  = fmaxf(fmaxf(l0, l1), fmaxf(l2, l3));
            float pv = tanhf(m);
            fl[p] = pv;
            int f = oc * 256 + ph2 * 128 + pw0 + p;
            float2 wv = *(const float2*)(Wout + 2 * f);
            d0 = fmaf(pv, wv.x, d0);
            d1 = fmaf(pv, wv.y, d1);
        }
        *(float4*)(flat + (size_t)b * 8192 + oc * 256 + ph2 * 128 + pw0)
            = make_float4(fl[0], fl[1], fl[2], fl[3]);
    }

    #pragma unroll
    for (int off = 16; off; off >>= 1) {
        d0 += __shfl_down_sync(0xffffffffu, d0, off);
        d1 += __shfl_down_sync(0xffffffffu, d1, off);
    }
    const int wid = t >> 5, lane = t & 31;
    if (lane == 0) { red[wid] = d0; red[8 + wid] = d1; }
    __syncthreads();
    if (t == 0) {
        float s0 = bout[0], s1 = bout[1];
        #pragma unroll
        for (int w = 0; w < 8; w++) { s0 += red[w]; s1 += red[8 + w]; }
        outp[2 * b]     = s0;
        outp[2 * b + 1] = s1;
    }
}

// ---------------------------------------------------------------------------
extern "C" void kernel_launch(void* const* d_in, const int* in_sizes, int n_in,
                              void* d_out, int out_size)
{
    const float* r_att   = (const float*)d_in[0];
    const float* p_att   = (const float*)d_in[1];
    const float* r_fun   = (const float*)d_in[2];
    const float* p_fun   = (const float*)d_in[3];
    const int*   idx     = (const int*)  d_in[4];
    const float* W_att1  = (const float*)d_in[5];
    const float* b_att1  = (const float*)d_in[6];
    const float* W_att2  = (const float*)d_in[7];
    const float* b_att2  = (const float*)d_in[8];
    const float* W_fun1  = (const float*)d_in[9];
    const float* b_fun1  = (const float*)d_in[10];
    const float* W_fun2  = (const float*)d_in[11];
    const float* b_fun2  = (const float*)d_in[12];
    const float* conv1_w = (const float*)d_in[13];
    const float* conv1_b = (const float*)d_in[14];
    const float* conv2_w = (const float*)d_in[15];
    const float* conv2_b = (const float*)d_in[16];
    const float* W_out   = (const float*)d_in[17];
    const float* b_out   = (const float*)d_in[18];

    float* e    = (float*)d_out;                       // [3512,512] = e_r | e_p
    float* outp = e + (size_t)NMTOT * 512;             // [8192,2]
    float* flat = outp + (size_t)BATCH * 2;            // [8192,8192]

    float* Pbuf = nullptr;  cudaGetSymbolAddress((void**)&Pbuf, g_P);
    __half *AhiA, *AloA, *AhiF, *AloF, *BA, *BF, *Hhi, *Hlo, *B2A, *B2F;
    cudaGetSymbolAddress((void**)&AhiA, g_Ahi_att);
    cudaGetSymbolAddress((void**)&AloA, g_Alo_att);
    cudaGetSymbolAddress((void**)&AhiF, g_Ahi_fun);
    cudaGetSymbolAddress((void**)&AloF, g_Alo_fun);
    cudaGetSymbolAddress((void**)&BA,   g_B_att);
    cudaGetSymbolAddress((void**)&BF,   g_B_fun);
    cudaGetSymbolAddress((void**)&Hhi,  g_Hhi);
    cudaGetSymbolAddress((void**)&Hlo,  g_Hlo);
    cudaGetSymbolAddress((void**)&B2A,  g_B2_att);
    cudaGetSymbolAddress((void**)&B2F,  g_B2_fun);

    const int smem_bytes = SMEM_FLOATS * sizeof(float);
    cudaFuncSetAttribute(conv_kernel,
                         cudaFuncAttributeMaxDynamicSharedMemorySize, smem_bytes);
    cudaFuncSetAttribute(gemm1_mma_kernel,
                         cudaFuncAttributeMaxDynamicSharedMemorySize, G1_SMEM);
    cudaFuncSetAttribute(gemm2_mma_kernel,
                         cudaFuncAttributeMaxDynamicSharedMemorySize, G1_SMEM);

    dim3 blk(256);
    const int mtiles = MPAD / 128;                     // 28

    // launches 0..2: prep needed by GEMM1
    split_cat2_kernel<<<dim3((KFUN_PAD + 255) / 256, MPAD, 2), blk>>>(
        r_att, p_att, r_fun, p_fun, AhiA, AloA, AhiF, AloF);
    tsplit_kernel<<<dim3(HATT / 32, KATT_PAD / 32), blk>>>(
        W_att1, KATT, HATT, KATT_PAD, BA);
    tsplit_kernel<<<dim3(HFUN / 32, KFUN_PAD / 32), blk>>>(
        W_fun1, KFUN, HFUN, KFUN_PAD, BF);

    // launch 3: GEMM1 (profiled slot)
    gemm1_mma_kernel<<<dim3(48, mtiles), blk, G1_SMEM>>>(
        AhiA, AloA, BA, b_att1, AhiF, AloF, BF, b_fun1, Hhi, Hlo);

    // launches 4..5: W2 transpose prep (needed only by GEMM2)
    tsplit_kernel<<<dim3(256 / 32, HATT / 32), blk>>>(
        W_att2, HATT, 256, HATT, B2A);
    tsplit_kernel<<<dim3(256 / 32, HFUN / 32), blk>>>(
        W_fun2, HFUN, 256, HFUN, B2F);

    // GEMM2 (split-K=8) + merged reduce+sigmoid
    gemm2_mma_kernel<<<dim3(4, mtiles, SPL2), blk, G1_SMEM>>>(
        Hhi, Hlo, B2A, B2F, Pbuf);
    reduce2_kernel<<<(NMTOT * 512 + 255) / 256, blk>>>(Pbuf, b_att2, b_fun2, e);

    // fused gather + conv pipeline
    conv_kernel<<<BATCH, blk, smem_bytes>>>(
        e, idx, conv1_w, conv1_b, conv2_w, conv2_b, W_out, b_out, outp, flat);
}

// round 16
// speedup vs baseline: 1.1891x; 1.1891x over previous
#include <cuda_runtime.h>
#include <cuda_fp16.h>
#include <math.h>
#include <stdint.h>

#define NRR   2000
#define NPP   1512
#define NMTOT 3512
#define MPAD  3584
#define KATT  3000
#define KFUN  5603
#define KATT_PAD 3008
#define KFUN_PAD 5632
#define HATT  2048
#define HFUN  4096
#define BATCH 8192
#define PROT  1512
#define SPL2  8

// ---------------- device scratch (fp16 GEMM path) ----------------
__device__ __align__(256) __half g_A_att[(size_t)MPAD * KATT_PAD];
__device__ __align__(256) __half g_A_fun[(size_t)MPAD * KFUN_PAD];
__device__ __align__(256) __half g_B_att[(size_t)HATT * KATT_PAD];
__device__ __align__(256) __half g_B_fun[(size_t)HFUN * KFUN_PAD];
// H in fp16 hi/lo: att rows [3584][2048] then fun rows [3584][4096]
__device__ __align__(256) __half g_Hhi[(size_t)MPAD * (HATT + HFUN)];
__device__ __align__(256) __half g_Hlo[(size_t)MPAD * (HATT + HFUN)];
// W2 transposed, single fp16
__device__ __align__(256) __half g_B2_att[(size_t)256 * HATT];
__device__ __align__(256) __half g_B2_fun[(size_t)256 * HFUN];
// split-K partials: [branch(2)][split(8)][3584][256]
__device__ float g_P[(size_t)2 * SPL2 * MPAD * 256];

__device__ __forceinline__ float gelu_f(float x) {
    return 0.5f * x * (1.0f + erff(x * 0.70710678118654752f));
}
__device__ __forceinline__ float sigmoid_f(float x) {
    return 1.0f / (1.0f + expf(-x));
}
__device__ __forceinline__ float leaky_f(float x) {
    return (x >= 0.f) ? x : 0.01f * x;
}

// ---- packed fp32x2 helpers (conv kernel) ----
__device__ __forceinline__ uint64_t pack2(float x) {
    uint64_t r; asm("mov.b64 %0, {%1, %1};" : "=l"(r) : "f"(x)); return r;
}
__device__ __forceinline__ uint64_t packf2(float lo, float hi) {
    uint64_t r; asm("mov.b64 %0, {%1, %2};" : "=l"(r) : "f"(lo), "f"(hi)); return r;
}
__device__ __forceinline__ void fma2(uint64_t& d, uint64_t a, uint64_t b) {
    asm("fma.rn.f32x2 %0, %1, %2, %0;" : "+l"(d) : "l"(a), "l"(b));
}
__device__ __forceinline__ float2 unpack2(uint64_t v) {
    float2 f; asm("mov.b64 {%0, %1}, %2;" : "=f"(f.x), "=f"(f.y) : "l"(v)); return f;
}

__device__ __forceinline__ uint32_t smem_u32(const void* p) {
    return (uint32_t)__cvta_generic_to_shared(p);
}
#define CPA16(dst, src) asm volatile("cp.async.cg.shared.global [%0], [%1], 16;" :: "r"(dst), "l"(src))
#define CPA_COMMIT()    asm volatile("cp.async.commit_group;")
#define CPA_WAIT2()     asm volatile("cp.async.wait_group 2;")

#define LDMX4(r, a) \
    asm volatile("ldmatrix.sync.aligned.m8n8.x4.shared.b16 {%0,%1,%2,%3}, [%4];" \
        : "=r"((r)[0]), "=r"((r)[1]), "=r"((r)[2]), "=r"((r)[3]) : "r"(a))

__device__ __forceinline__ void mma_fp16(float* d,
                                         uint32_t a0, uint32_t a1, uint32_t a2, uint32_t a3,
                                         uint32_t b0, uint32_t b1) {
    asm volatile(
        "mma.sync.aligned.m16n8k16.row.col.f32.f16.f16.f32 "
        "{%0,%1,%2,%3}, {%4,%5,%6,%7}, {%8,%9}, {%0,%1,%2,%3};"
        : "+f"(d[0]), "+f"(d[1]), "+f"(d[2]), "+f"(d[3])
        : "r"(a0), "r"(a1), "r"(a2), "r"(a3), "r"(b0), "r"(b1));
}

// ===========================================================================
// Prep 1: convert fp32 activations (row-concat + pad) to single fp16.
// blockIdx.z = 0 -> att, 1 -> fun. ONE launch.
// ===========================================================================
__global__ void split_cat2_kernel(const float* __restrict__ rA, const float* __restrict__ pA,
                                  const float* __restrict__ rF, const float* __restrict__ pF,
                                  __half* __restrict__ DA, __half* __restrict__ DF)
{
    const int br = blockIdx.z;
    const int K    = br ? KFUN : KATT;
    const int Kpad = br ? KFUN_PAD : KATT_PAD;
    const float* S0 = br ? rF : rA;
    const float* S1 = br ? pF : pA;
    __half* D = br ? DF : DA;

    int k = blockIdx.x * 256 + threadIdx.x;
    int m = blockIdx.y;
    if (k >= Kpad) return;
    float x = 0.f;
    if (k < K && m < NMTOT)
        x = (m < NRR) ? S0[(size_t)m * K + k] : S1[(size_t)(m - NRR) * K + k];
    D[(size_t)m * Kpad + k] = __float2half_rn(x);
}

// ===========================================================================
// Prep 2: transpose weights W[K,N] -> single fp16 [N, Kpad].
// ===========================================================================
__global__ void tsplit_kernel(const float* __restrict__ W, int K, int N, int Kpad,
                              __half* __restrict__ D)
{
    __shared__ float tile[32][33];
    const int t = threadIdx.x;
    const int tx = t & 31, ty = t >> 5;
    const int kb = blockIdx.y * 32, nb = blockIdx.x * 32;
    #pragma unroll
    for (int r = 0; r < 4; r++) {
        int kl = ty + 8 * r;
        int gk = kb + kl;
        tile[kl][tx] = (gk < K) ? W[(size_t)gk * N + nb + tx] : 0.f;
    }
    __syncthreads();
    #pragma unroll
    for (int r = 0; r < 4; r++) {
        int nl = ty + 8 * r;
        D[(size_t)(nb + nl) * Kpad + kb + tx] = __float2half_rn(tile[tx][nl]);
    }
}

// ===========================================================================
// Shared mma.sync mainloop, templated on NPROD (1 or 2 A-products).
// CTA 128x128, 8 warps (4m x 2n), warp tile 32x64, BK=32 stages
// (NPROD A tiles + B tile, 8KB each), 4-stage cp.async pipeline,
// ldmatrix fragment loads.
// ===========================================================================
template<int NPROD>
__device__ __forceinline__ void mma_mainloop(
    uint32_t sb, int t,
    const __half* __restrict__ Ahi, const __half* __restrict__ Alo,
    const __half* __restrict__ B,
    int Kpad, int kb, int C, int m0, int n0,
    float acc[2][8][4])
{
    constexpr int STAGE = (NPROD + 1) * 8192;
    const int lane = t & 31;
    const int wid  = t >> 5;
    const int wm   = wid & 3;
    const int wn   = wid >> 2;

    auto load_stage = [&](int c, int s) {
        const int kc = kb + c * 32;
        const uint32_t dstb = sb + (uint32_t)s * STAGE;
        #pragma unroll
        for (int j = 0; j < 2 * (NPROD + 1); j++) {
            int cg  = t + 256 * j;
            int mat = cg >> 9;              // 0..NPROD-1: A parts, NPROD: B
            int idx = cg & 511;
            int row = idx >> 2;
            int ch  = idx & 3;
            int sw  = (row ^ (row >> 2)) & 3;
            uint32_t dst = dstb + (uint32_t)(mat * 8192 + row * 64 + ((ch ^ sw) << 4));
            const __half* src =
                (mat == NPROD ? B   + (size_t)(n0 + row) * Kpad :
                 mat == 0     ? Ahi + (size_t)(m0 + row) * Kpad :
                                Alo + (size_t)(m0 + row) * Kpad) + kc + ch * 8;
            CPA16(dst, src);
        }
        CPA_COMMIT();
    };

    auto compute_stage = [&](int s) {
        const uint32_t Ab = sb + (uint32_t)s * STAGE;
        const uint32_t Bb = Ab + NPROD * 8192;
        #pragma unroll
        for (int kk = 0; kk < 2; kk++) {
            uint32_t ah[2][4], al[2][4], bf[4][4];
            {
                uint32_t arow0 = (uint32_t)(wm * 32 + (lane & 7) + ((lane >> 3) & 1) * 8);
                uint32_t achnk = (uint32_t)(2 * kk + (lane >> 4));
                #pragma unroll
                for (int T = 0; T < 2; T++) {
                    uint32_t r  = arow0 + T * 16;
                    uint32_t sw = (r ^ (r >> 2)) & 3;
                    uint32_t a  = Ab + r * 64 + ((achnk ^ sw) << 4);
                    LDMX4(ah[T], a);
                    if (NPROD == 2) LDMX4(al[T], a + 8192);
                }
            }
            {
                uint32_t brow0 = (uint32_t)(wn * 64 + ((lane >> 4) & 1) * 8 + (lane & 7));
                uint32_t bchnk = (uint32_t)(2 * kk + ((lane >> 3) & 1));
                #pragma unroll
                for (int p = 0; p < 4; p++) {
                    uint32_t r  = brow0 + 16 * p;
                    uint32_t sw = (r ^ (r >> 2)) & 3;
                    LDMX4(bf[p], Bb + r * 64 + ((bchnk ^ sw) << 4));
                }
            }
            #pragma unroll
            for (int p = 0; p < 4; p++)
                #pragma unroll
                for (int hf = 0; hf < 2; hf++)
                    #pragma unroll
                    for (int T = 0; T < 2; T++)
                        mma_fp16(acc[T][2 * p + hf],
                                 ah[T][0], ah[T][1], ah[T][2], ah[T][3],
                                 bf[p][2 * hf], bf[p][2 * hf + 1]);
            if (NPROD == 2) {
                #pragma unroll
                for (int p = 0; p < 4; p++)
                    #pragma unroll
                    for (int hf = 0; hf < 2; hf++)
                        #pragma unroll
                        for (int T = 0; T < 2; T++)
                            mma_fp16(acc[T][2 * p + hf],
                                     al[T][0], al[T][1], al[T][2], al[T][3],
                                     bf[p][2 * hf], bf[p][2 * hf + 1]);
            }
        }
    };

    load_stage(0, 0);
    if (C > 1) load_stage(1, 1); else CPA_COMMIT();
    if (C > 2) load_stage(2, 2); else CPA_COMMIT();

    for (int c = 0; c < C; c++) {
        CPA_WAIT2();
        __syncthreads();
        if (c + 3 < C) load_stage(c + 3, (c + 3) & 3);
        else CPA_COMMIT();
        compute_stage(c & 3);
    }
}

#define G1_SMEM (4 * 16384)
#define G2_SMEM (4 * 24576)

// ===========================================================================
// GEMM1 (single fp16 A): H = gelu(X W1 + b1) -> fp16 hi/lo. bx<16 att else fun
// ===========================================================================
__global__ __launch_bounds__(256, 2)
void gemm1_mma_kernel(const __half* __restrict__ AA, const __half* __restrict__ BA,
                      const float* __restrict__ biasA,
                      const __half* __restrict__ AF, const __half* __restrict__ BF,
                      const float* __restrict__ biasF,
                      __half* __restrict__ Hhi, __half* __restrict__ Hlo)
{
    extern __shared__ char smraw[];
    const uint32_t sb = smem_u32(smraw);
    const int t = threadIdx.x;
    const int lane = t & 31, wid = t >> 5, wm = wid & 3, wn = wid >> 2;
    const int g = lane >> 2, tq = lane & 3;
    const int m0 = blockIdx.y * 128;

    const __half *A, *B;
    const float* bias;
    __half *Hh, *Hl;
    int Kpad, ldH, n0;
    if (blockIdx.x < 16) {
        A = AA; B = BA; bias = biasA;
        Hh = Hhi; Hl = Hlo; Kpad = KATT_PAD; ldH = HATT; n0 = blockIdx.x * 128;
    } else {
        A = AF; B = BF; bias = biasF;
        Hh = Hhi + (size_t)MPAD * HATT; Hl = Hlo + (size_t)MPAD * HATT;
        Kpad = KFUN_PAD; ldH = HFUN; n0 = (blockIdx.x - 16) * 128;
    }

    float acc[2][8][4];
    #pragma unroll
    for (int T = 0; T < 2; T++)
        #pragma unroll
        for (int n8 = 0; n8 < 8; n8++)
            #pragma unroll
            for (int q = 0; q < 4; q++) acc[T][n8][q] = 0.f;

    mma_mainloop<1>(sb, t, A, nullptr, B, Kpad, 0, Kpad >> 5, m0, n0, acc);

    // epilogue: gelu(bias+acc) -> fp16 hi/lo
    #pragma unroll
    for (int T = 0; T < 2; T++) {
        const int r0 = m0 + wm * 32 + T * 16 + g;
        const int r1 = r0 + 8;
        #pragma unroll
        for (int n8 = 0; n8 < 8; n8++) {
            const int col = n0 + wn * 64 + n8 * 8 + 2 * tq;
            const float b0 = bias[col], b1 = bias[col + 1];
            if (r0 < NMTOT) {
                float v0 = gelu_f(acc[T][n8][0] + b0);
                float v1 = gelu_f(acc[T][n8][1] + b1);
                __half2 h, l;
                h.x = __float2half_rn(v0); h.y = __float2half_rn(v1);
                l.x = __float2half_rn(v0 - __half2float(h.x));
                l.y = __float2half_rn(v1 - __half2float(h.y));
                *(__half2*)(Hh + (size_t)r0 * ldH + col) = h;
                *(__half2*)(Hl + (size_t)r0 * ldH + col) = l;
            }
            if (r1 < NMTOT) {
                float v0 = gelu_f(acc[T][n8][2] + b0);
                float v1 = gelu_f(acc[T][n8][3] + b1);
                __half2 h, l;
                h.x = __float2half_rn(v0); h.y = __float2half_rn(v1);
                l.x = __float2half_rn(v0 - __half2float(h.x));
                l.y = __float2half_rn(v1 - __half2float(h.y));
                *(__half2*)(Hh + (size_t)r1 * ldH + col) = h;
                *(__half2*)(Hl + (size_t)r1 * ldH + col) = l;
            }
        }
    }
}

// ===========================================================================
// GEMM2 (2-product H split, split-K partials): bx = branch*2 + ntile, bz slice
// ===========================================================================
__global__ __launch_bounds__(256, 2)
void gemm2_mma_kernel(const __half* __restrict__ Hhi, const __half* __restrict__ Hlo,
                      const __half* __restrict__ B2A, const __half* __restrict__ B2F,
                      float* __restrict__ P)
{
    extern __shared__ char smraw[];
    const uint32_t sb = smem_u32(smraw);
    const int t = threadIdx.x;
    const int lane = t & 31, wid = t >> 5, wm = wid & 3, wn = wid >> 2;
    const int g = lane >> 2, tq = lane & 3;
    const int m0 = blockIdx.y * 128;

    const int branch = blockIdx.x >> 1;
    const int n0     = (blockIdx.x & 1) * 128;
    const int sl     = blockIdx.z;

    const __half *Ahi, *Alo, *B;
    int K;
    if (branch == 0) {
        Ahi = Hhi; Alo = Hlo; B = B2A; K = HATT;
    } else {
        Ahi = Hhi + (size_t)MPAD * HATT; Alo = Hlo + (size_t)MPAD * HATT;
        B = B2F; K = HFUN;
    }
    const int chunk = K / SPL2;
    const int kb = sl * chunk;

    float acc[2][8][4];
    #pragma unroll
    for (int T = 0; T < 2; T++)
        #pragma unroll
        for (int n8 = 0; n8 < 8; n8++)
            #pragma unroll
            for (int q = 0; q < 4; q++) acc[T][n8][q] = 0.f;

    mma_mainloop<2>(sb, t, Ahi, Alo, B, K, kb, chunk >> 5, m0, n0, acc);

    float* Pd = P + ((size_t)(branch * SPL2 + sl) * MPAD) * 256;
    #pragma unroll
    for (int T = 0; T < 2; T++) {
        const int r0 = m0 + wm * 32 + T * 16 + g;
        const int r1 = r0 + 8;
        #pragma unroll
        for (int n8 = 0; n8 < 8; n8++) {
            const int col = n0 + wn * 64 + n8 * 8 + 2 * tq;
            *(float2*)(Pd + (size_t)r0 * 256 + col) = make_float2(acc[T][n8][0], acc[T][n8][1]);
            *(float2*)(Pd + (size_t)r1 * 256 + col) = make_float2(acc[T][n8][2], acc[T][n8][3]);
        }
    }
}

// Reduce split-K partials (both branches), add bias, sigmoid -> e[3512,512].
__global__ void reduce2_kernel(const float* __restrict__ P,
                               const float* __restrict__ biasA,
                               const float* __restrict__ biasF,
                               float* __restrict__ e)
{
    int i = blockIdx.x * 256 + threadIdx.x;
    if (i >= NMTOT * 512) return;
    int m = i >> 9, n = i & 511;
    int br = n >> 8, col = n & 255;
    float v = br ? biasF[col] : biasA[col];
    #pragma unroll
    for (int s = 0; s < SPL2; s++)
        v += P[((size_t)(br * SPL2 + s) * MPAD + m) * 256 + col];
    e[i] = sigmoid_f(v);
}

// ---------------------------------------------------------------------------
// Fused per-sample conv pipeline (unchanged, proven).
// ---------------------------------------------------------------------------
#define SX_STRIDE 520
#define A1_STRIDE 264
#define W2_STRIDE 245

#define SMEM_FLOATS (2*SX_STRIDE + 32*A1_STRIDE + 32*W2_STRIDE + 240 + 16)

__global__ __launch_bounds__(256)
void conv_kernel(const float* __restrict__ e,
                 const int* __restrict__ idx,
                 const float* __restrict__ w1g,
                 const float* __restrict__ b1,
                 const float* __restrict__ w2g,
                 const float* __restrict__ b2,
                 const float* __restrict__ Wout,
                 const float* __restrict__ bout,
                 float* __restrict__ outp,
                 float* __restrict__ flat)
{
    extern __shared__ float sm[];
    float* sx  = sm;
    float* a1s = sx  + 2 * SX_STRIDE;
    float* w2s = a1s + 32 * A1_STRIDE;
    float* w1s = w2s + 32 * W2_STRIDE;
    float* red = w1s + 240;

    const int t = threadIdx.x;
    const int b = blockIdx.x;

    for (int i = t; i < 2 * SX_STRIDE;  i += 256) sx[i]  = 0.f;
    for (int i = t; i < 32 * A1_STRIDE; i += 256) a1s[i] = 0.f;
    for (int i = t; i < 240; i += 256) w1s[i] = w1g[i];
    for (int i = t; i < 32 * 240; i += 256) {
        int oc = i / 240, r = i - oc * 240;
        w2s[oc * W2_STRIDE + r] = w2g[i];
    }
    const int id  = idx[b];
    const int rno = id / PROT;
    const int pno = id % PROT;
    __syncthreads();

    {
        const float* er = e + (size_t)rno * 512;
        const float* ep = e + (size_t)(NRR + pno) * 512;
        for (int i = t; i < 512; i += 256) {
            sx[0 * SX_STRIDE + 2 + i] = er[i];
            sx[1 * SX_STRIDE + 2 + i] = ep[i];
        }
    }
    __syncthreads();

    for (int j = 0; j < 32; j++) {
        int i   = t + 256 * j;
        int c   = i >> 9;
        int rem = i & 511;
        int ph  = rem >> 8;
        int pw  = rem & 255;
        const float* w = w1s + c * 15;
        float bias1 = b1[c];
        float s = 0.f;
        #pragma unroll
        for (int dh = 0; dh < 2; dh++) {
            int oh = 2 * ph + dh;
            #pragma unroll
            for (int dw = 0; dw < 2; dw++) {
                int ow = 2 * pw + dw;
                float cv = bias1;
                #pragma unroll
                for (int ih = 0; ih < 2; ih++) {
                    int kh = ih - oh + 2;
                    if (kh >= 0 && kh <= 2) {
                        const float* xr = sx + ih * SX_STRIDE + ow;
                        #pragma unroll
                        for (int kw = 0; kw < 5; kw++)
                            cv = fmaf(xr[kw], w[kh * 5 + kw], cv);
                    }
                }
                s += leaky_f(cv);
            }
        }
        a1s[(c * 2 + ph) * A1_STRIDE + pw + 2] = 0.25f * s;
    }
    __syncthreads();

    const int ph2 = t >> 7;
    const int oc  = (t >> 2) & 31;
    const int q   = t & 3;
    const float bias2 = b2[oc];
    const float* wbase = w2s + oc * W2_STRIDE;

    float d0 = 0.f, d1 = 0.f;

    for (int it = 0; it < 8; it++) {
        const int chunk = it * 4 + q;
        const int pw0   = chunk * 4;
        const int iwoff = chunk * 8;

        uint64_t accp0[4], accp1[4];
        #pragma unroll
        for (int p = 0; p < 4; p++) { accp0[p] = 0ull; accp1[p] = 0ull; }

        for (int ci = 0; ci < 16; ci++) {
            uint64_t wp[15];
            {
                const float* w = wbase + ci * 15;
                #pragma unroll
                for (int k = 0; k < 15; k++) wp[k] = pack2(w[k]);
            }

            float r0f[12], r1f[12];
            {
                const float* p0 = a1s + (ci * 2 + 0) * A1_STRIDE + iwoff;
                const float* p1 = p0 + A1_STRIDE;
                #pragma unroll
                for (int v = 0; v < 3; v++) {
                    float4 u0 = *(const float4*)(p0 + 4 * v);
                    float4 u1 = *(const float4*)(p1 + 4 * v);
                    r0f[4*v] = u0.x; r0f[4*v+1] = u0.y; r0f[4*v+2] = u0.z; r0f[4*v+3] = u0.w;
                    r1f[4*v] = u1.x; r1f[4*v+1] = u1.y; r1f[4*v+2] = u1.z; r1f[4*v+3] = u1.w;
                }
            }
            uint64_t rp0[11], rp1[11];
            #pragma unroll
            for (int k = 0; k < 11; k++) {
                rp0[k] = packf2(r0f[k], r0f[k + 1]);
                rp1[k] = packf2(r1f[k], r1f[k + 1]);
            }

            if (ph2 == 0) {
                #pragma unroll
                for (int p = 0; p < 4; p++) {
                    const int j = 2 * p;
                    #pragma unroll
                    for (int kw = 0; kw < 5; kw++) {
                        fma2(accp0[p], rp0[j + kw], wp[10 + kw]);
                        fma2(accp1[p], rp0[j + kw], wp[5 + kw]);
                        fma2(accp1[p], rp1[j + kw], wp[10 + kw]);
                    }
                }
            } else {
                #pragma unroll
                for (int p = 0; p < 4; p++) {
                    const int j = 2 * p;
                    #pragma unroll
                    for (int kw = 0; kw < 5; kw++) {
                        fma2(accp0[p], rp0[j + kw], wp[kw]);
                        fma2(accp0[p], rp1[j + kw], wp[5 + kw]);
                        fma2(accp1[p], rp1[j + kw], wp[kw]);
                    }
                }
            }
        }

        float fl[4];
        #pragma unroll
        for (int p = 0; p < 4; p++) {
            float2 v0 = unpack2(accp0[p]);
            float2 v1 = unpack2(accp1[p]);
            float l0 = leaky_f(v0.x + bias2);
            float l1 = leaky_f(v0.y + bias2);
            float l2 = leaky_f(v1.x + bias2);
            float l3 = leaky_f(v1.y + bias2);
            float m  = fmaxf(fmaxf(l0, l1), fmaxf(l2, l3));
            float pv = tanhf(m);
            fl[p] = pv;
            int f = oc * 256 + ph2 * 128 + pw0 + p;
            float2 wv = *(const float2*)(Wout + 2 * f);
            d0 = fmaf(pv, wv.x, d0);
            d1 = fmaf(pv, wv.y, d1);
        }
        *(float4*)(flat + (size_t)b * 8192 + oc * 256 + ph2 * 128 + pw0)
            = make_float4(fl[0], fl[1], fl[2], fl[3]);
    }

    #pragma unroll
    for (int off = 16; off; off >>= 1) {
        d0 += __shfl_down_sync(0xffffffffu, d0, off);
        d1 += __shfl_down_sync(0xffffffffu, d1, off);
    }
    const int wid = t >> 5, lane = t & 31;
    if (lane == 0) { red[wid] = d0; red[8 + wid] = d1; }
    __syncthreads();
    if (t == 0) {
        float s0 = bout[0], s1 = bout[1];
        #pragma unroll
        for (int w = 0; w < 8; w++) { s0 += red[w]; s1 += red[8 + w]; }
        outp[2 * b]     = s0;
        outp[2 * b + 1] = s1;
    }
}

// ---------------------------------------------------------------------------
extern "C" void kernel_launch(void* const* d_in, const int* in_sizes, int n_in,
                              void* d_out, int out_size)
{
    const float* r_att   = (const float*)d_in[0];
    const float* p_att   = (const float*)d_in[1];
    const float* r_fun   = (const float*)d_in[2];
    const float* p_fun   = (const float*)d_in[3];
    const int*   idx     = (const int*)  d_in[4];
    const float* W_att1  = (const float*)d_in[5];
    const float* b_att1  = (const float*)d_in[6];
    const float* W_att2  = (const float*)d_in[7];
    const float* b_att2  = (const float*)d_in[8];
    const float* W_fun1  = (const float*)d_in[9];
    const float* b_fun1  = (const float*)d_in[10];
    const float* W_fun2  = (const float*)d_in[11];
    const float* b_fun2  = (const float*)d_in[12];
    const float* conv1_w = (const float*)d_in[13];
    const float* conv1_b = (const float*)d_in[14];
    const float* conv2_w = (const float*)d_in[15];
    const float* conv2_b = (const float*)d_in[16];
    const float* W_out   = (const float*)d_in[17];
    const float* b_out   = (const float*)d_in[18];

    float* e    = (float*)d_out;                       // [3512,512] = e_r | e_p
    float* outp = e + (size_t)NMTOT * 512;             // [8192,2]
    float* flat = outp + (size_t)BATCH * 2;            // [8192,8192]

    float* Pbuf = nullptr;  cudaGetSymbolAddress((void**)&Pbuf, g_P);
    __half *AA, *AF, *BA, *BF, *Hhi, *Hlo, *B2A, *B2F;
    cudaGetSymbolAddress((void**)&AA,  g_A_att);
    cudaGetSymbolAddress((void**)&AF,  g_A_fun);
    cudaGetSymbolAddress((void**)&BA,  g_B_att);
    cudaGetSymbolAddress((void**)&BF,  g_B_fun);
    cudaGetSymbolAddress((void**)&Hhi, g_Hhi);
    cudaGetSymbolAddress((void**)&Hlo, g_Hlo);
    cudaGetSymbolAddress((void**)&B2A, g_B2_att);
    cudaGetSymbolAddress((void**)&B2F, g_B2_fun);

    const int smem_bytes = SMEM_FLOATS * sizeof(float);
    cudaFuncSetAttribute(conv_kernel,
                         cudaFuncAttributeMaxDynamicSharedMemorySize, smem_bytes);
    cudaFuncSetAttribute(gemm1_mma_kernel,
                         cudaFuncAttributeMaxDynamicSharedMemorySize, G1_SMEM);
    cudaFuncSetAttribute(gemm2_mma_kernel,
                         cudaFuncAttributeMaxDynamicSharedMemorySize, G2_SMEM);

    dim3 blk(256);
    const int mtiles = MPAD / 128;                     // 28

    // launches 0..2: prep needed by GEMM1
    split_cat2_kernel<<<dim3((KFUN_PAD + 255) / 256, MPAD, 2), blk>>>(
        r_att, p_att, r_fun, p_fun, AA, AF);
    tsplit_kernel<<<dim3(HATT / 32, KATT_PAD / 32), blk>>>(
        W_att1, KATT, HATT, KATT_PAD, BA);
    tsplit_kernel<<<dim3(HFUN / 32, KFUN_PAD / 32), blk>>>(
        W_fun1, KFUN, HFUN, KFUN_PAD, BF);

    // launch 3: GEMM1 (profiled slot)
    gemm1_mma_kernel<<<dim3(48, mtiles), blk, G1_SMEM>>>(
        AA, BA, b_att1, AF, BF, b_fun1, Hhi, Hlo);

    // launches 4..5: W2 transpose prep (needed only by GEMM2)
    tsplit_kernel<<<dim3(256 / 32, HATT / 32), blk>>>(
        W_att2, HATT, 256, HATT, B2A);
    tsplit_kernel<<<dim3(256 / 32, HFUN / 32), blk>>>(
        W_fun2, HFUN, 256, HFUN, B2F);

    // GEMM2 (split-K=8) + merged reduce+sigmoid
    gemm2_mma_kernel<<<dim3(4, mtiles, SPL2), blk, G2_SMEM>>>(
        Hhi, Hlo, B2A, B2F, Pbuf);
    reduce2_kernel<<<(NMTOT * 512 + 255) / 256, blk>>>(Pbuf, b_att2, b_fun2, e);

    // fused gather + conv pipeline
    conv_kernel<<<BATCH, blk, smem_bytes>>>(
        e, idx, conv1_w, conv1_b, conv2_w, conv2_b, W_out, b_out, outp, flat);
}